// round 2
// baseline (speedup 1.0000x reference)
#include <cuda_runtime.h>
#include <math_constants.h>

// TropicalLinear forward on GB300:
//   out[n,o] = max_j( x[n,j] + w[o,j] ) + bias[o]
// (soft - stop_gradient(soft) == 0 in forward numerics)

#define N_DIM   128
#define IN_DIM  1024
#define OUT_DIM 1024
#define KSPLIT  4
#define BM      64
#define BO      64
#define BK      32
#define SSTRIDE 36   // smem row stride in floats (144B = 9*16B, keeps float4 align, 2-way conflicts max)

// split-K partial maxima scratch (no allocations allowed -> device global)
__device__ float g_partial[KSPLIT * N_DIM * OUT_DIM];

__global__ __launch_bounds__(256, 1)
void tropical_partial_kernel(const float* __restrict__ x,
                             const float* __restrict__ w)
{
    __shared__ float xs[BM * SSTRIDE];
    __shared__ float ws[BO * SSTRIDE];

    const int t  = threadIdx.x;
    const int tx = t & 15;        // o-group
    const int ty = t >> 4;        // n-group
    const int oBase = blockIdx.x * BO;
    const int nBase = blockIdx.y * BM;
    const int kBase = blockIdx.z * (IN_DIM / KSPLIT);

    float acc[4][4];
#pragma unroll
    for (int r = 0; r < 4; r++)
#pragma unroll
        for (int c = 0; c < 4; c++)
            acc[r][c] = -CUDART_INF_F;

    for (int kc = 0; kc < IN_DIM / KSPLIT; kc += BK) {
        // ---- load tiles: x[BM][BK], w[BO][BK]; 512 float4 each, 2 per thread ----
#pragma unroll
        for (int i = 0; i < 2; i++) {
            int idx = t + i * 256;        // 0..511
            int row = idx >> 3;           // 64 rows, 8 float4/row
            int kk  = (idx & 7) << 2;     // 0..28
            const float4 xv = *(const float4*)&x[(nBase + row) * IN_DIM + kBase + kc + kk];
            *(float4*)&xs[row * SSTRIDE + kk] = xv;
            const float4 wv = *(const float4*)&w[(oBase + row) * IN_DIM + kBase + kc + kk];
            *(float4*)&ws[row * SSTRIDE + kk] = wv;
        }
        __syncthreads();

        // ---- compute: vectorize along k by 4 ----
#pragma unroll
        for (int k4 = 0; k4 < BK / 4; k4++) {
            float4 xv[4], wv[4];
#pragma unroll
            for (int r = 0; r < 4; r++)
                xv[r] = *(const float4*)&xs[(ty + 16 * r) * SSTRIDE + k4 * 4];
#pragma unroll
            for (int c = 0; c < 4; c++)
                wv[c] = *(const float4*)&ws[(tx + 16 * c) * SSTRIDE + k4 * 4];
#pragma unroll
            for (int r = 0; r < 4; r++)
#pragma unroll
                for (int c = 0; c < 4; c++) {
                    acc[r][c] = fmaxf(acc[r][c], xv[r].x + wv[c].x);
                    acc[r][c] = fmaxf(acc[r][c], xv[r].y + wv[c].y);
                    acc[r][c] = fmaxf(acc[r][c], xv[r].z + wv[c].z);
                    acc[r][c] = fmaxf(acc[r][c], xv[r].w + wv[c].w);
                }
        }
        __syncthreads();
    }

    float* p = g_partial + (size_t)blockIdx.z * (N_DIM * OUT_DIM);
#pragma unroll
    for (int r = 0; r < 4; r++)
#pragma unroll
        for (int c = 0; c < 4; c++) {
            int n = nBase + ty + 16 * r;
            int o = oBase + tx + 16 * c;
            p[n * OUT_DIM + o] = acc[r][c];
        }
}

__global__ __launch_bounds__(256, 1)
void tropical_combine_kernel(const float* __restrict__ bias,
                             float* __restrict__ out)
{
    // 128*1024 floats = 32768 float4; grid 128 x 256 threads, 1 float4/thread
    const int i = blockIdx.x * blockDim.x + threadIdx.x;   // float4 index
    const int S = (N_DIM * OUT_DIM) / 4;                   // split stride in float4

    const float4* p = (const float4*)g_partial;
    float4 a = p[i];
    float4 b = p[i + S];
    float4 c = p[i + 2 * S];
    float4 d = p[i + 3 * S];

    float4 bv = ((const float4*)bias)[i & (OUT_DIM / 4 - 1)];

    float4 r;
    r.x = fmaxf(fmaxf(a.x, b.x), fmaxf(c.x, d.x)) + bv.x;
    r.y = fmaxf(fmaxf(a.y, b.y), fmaxf(c.y, d.y)) + bv.y;
    r.z = fmaxf(fmaxf(a.z, b.z), fmaxf(c.z, d.z)) + bv.z;
    r.w = fmaxf(fmaxf(a.w, b.w), fmaxf(c.w, d.w)) + bv.w;

    ((float4*)out)[i] = r;
}

extern "C" void kernel_launch(void* const* d_in, const int* in_sizes, int n_in,
                              void* d_out, int out_size)
{
    const float* x    = (const float*)d_in[0];   // [128, 1024]
    const float* w    = (const float*)d_in[1];   // [1024, 1024]
    const float* bias = (const float*)d_in[2];   // [1024]
    float* out = (float*)d_out;                  // [128, 1024]

    dim3 grid1(OUT_DIM / BO, N_DIM / BM, KSPLIT);   // 16 x 2 x 4 = 128 blocks
    tropical_partial_kernel<<<grid1, 256>>>(x, w);

    tropical_combine_kernel<<<(N_DIM * OUT_DIM / 4) / 256, 256>>>(bias, out);
}

// round 4
// speedup vs baseline: 1.2786x; 1.2786x over previous
#include <cuda_runtime.h>
#include <math_constants.h>

// TropicalLinear forward: out[n,o] = max_j( x[n,j] + w[o,j] ) + bias[o]
// (soft - stop_gradient(soft) == 0 in forward numerics)
//
// Single kernel, no split-K: 32x32 output tiles -> 128 blocks.
// 256 threads, 2x2 register tile per thread (rows ty/ty+16, cols tx/tx+16).
// Double-buffered smem (BK=64), XOR-swizzled 16B slots, one sync per iter.

#define N_DIM   128
#define IN_DIM  1024
#define OUT_DIM 1024
#define BM      32
#define BO      32
#define BK      64
#define NITER   (IN_DIM / BK)   // 16

// float index of 16B slot c4 (0..15) of row r (0..31), XOR swizzle by row
#define SW(r, c4) ((((r) << 4) + ((c4) ^ ((r) & 15))) << 2)

__global__ __launch_bounds__(256, 1)
void tropical_kernel(const float* __restrict__ x,
                     const float* __restrict__ w,
                     const float* __restrict__ bias,
                     float* __restrict__ out)
{
    // two buffers, each 32 rows x 64 floats, for x-tile and w-tile: 32KB total
    __shared__ float xs[2][BM * BK];
    __shared__ float ws[2][BO * BK];

    const int t  = threadIdx.x;
    const int tx = t & 15;        // o group: cols tx, tx+16
    const int ty = t >> 4;        // n group: rows ty, ty+16
    const int oBase = blockIdx.x * BO;
    const int nBase = blockIdx.y * BM;

    // loader mapping: thread loads rows (ty, ty+16), 16B column tx, for both tiles
    const float* xg = x + (nBase + ty) * IN_DIM + (tx << 2);
    const float* wg = w + (oBase + ty) * IN_DIM + (tx << 2);

    float acc00 = -CUDART_INF_F, acc01 = -CUDART_INF_F;
    float acc10 = -CUDART_INF_F, acc11 = -CUDART_INF_F;

    float4 xr0, xr1, wr0, wr1;

    // ---- prologue: load tile 0 into buffer 0 ----
    xr0 = *(const float4*)(xg);
    xr1 = *(const float4*)(xg + 16 * IN_DIM);
    wr0 = *(const float4*)(wg);
    wr1 = *(const float4*)(wg + 16 * IN_DIM);
    *(float4*)&xs[0][SW(ty,      tx)] = xr0;
    *(float4*)&xs[0][SW(ty + 16, tx)] = xr1;
    *(float4*)&ws[0][SW(ty,      tx)] = wr0;
    *(float4*)&ws[0][SW(ty + 16, tx)] = wr1;
    __syncthreads();

#pragma unroll 1
    for (int i = 0; i < NITER - 1; i++) {
        const int b = i & 1;

        // prefetch next tile (LDGs issued before compute; latency hidden)
        const float* xp = xg + (i + 1) * BK;
        const float* wp = wg + (i + 1) * BK;
        xr0 = *(const float4*)(xp);
        xr1 = *(const float4*)(xp + 16 * IN_DIM);
        wr0 = *(const float4*)(wp);
        wr1 = *(const float4*)(wp + 16 * IN_DIM);

        // compute on buffer b
#pragma unroll
        for (int k4 = 0; k4 < BK / 4; k4++) {
            const float4 xv0 = *(const float4*)&xs[b][SW(ty,      k4)];
            const float4 xv1 = *(const float4*)&xs[b][SW(ty + 16, k4)];
            const float4 wv0 = *(const float4*)&ws[b][SW(tx,      k4)];
            const float4 wv1 = *(const float4*)&ws[b][SW(tx + 16, k4)];
            acc00 = fmaxf(acc00, xv0.x + wv0.x); acc00 = fmaxf(acc00, xv0.y + wv0.y);
            acc00 = fmaxf(acc00, xv0.z + wv0.z); acc00 = fmaxf(acc00, xv0.w + wv0.w);
            acc01 = fmaxf(acc01, xv0.x + wv1.x); acc01 = fmaxf(acc01, xv0.y + wv1.y);
            acc01 = fmaxf(acc01, xv0.z + wv1.z); acc01 = fmaxf(acc01, xv0.w + wv1.w);
            acc10 = fmaxf(acc10, xv1.x + wv0.x); acc10 = fmaxf(acc10, xv1.y + wv0.y);
            acc10 = fmaxf(acc10, xv1.z + wv0.z); acc10 = fmaxf(acc10, xv1.w + wv0.w);
            acc11 = fmaxf(acc11, xv1.x + wv1.x); acc11 = fmaxf(acc11, xv1.y + wv1.y);
            acc11 = fmaxf(acc11, xv1.z + wv1.z); acc11 = fmaxf(acc11, xv1.w + wv1.w);
        }

        // stage prefetched tile into the other buffer
        const int nb = b ^ 1;
        *(float4*)&xs[nb][SW(ty,      tx)] = xr0;
        *(float4*)&xs[nb][SW(ty + 16, tx)] = xr1;
        *(float4*)&ws[nb][SW(ty,      tx)] = wr0;
        *(float4*)&ws[nb][SW(ty + 16, tx)] = wr1;
        __syncthreads();
    }

    // ---- final tile: buffer (NITER-1)&1 = 1 ----
    {
        const int b = (NITER - 1) & 1;
#pragma unroll
        for (int k4 = 0; k4 < BK / 4; k4++) {
            const float4 xv0 = *(const float4*)&xs[b][SW(ty,      k4)];
            const float4 xv1 = *(const float4*)&xs[b][SW(ty + 16, k4)];
            const float4 wv0 = *(const float4*)&ws[b][SW(tx,      k4)];
            const float4 wv1 = *(const float4*)&ws[b][SW(tx + 16, k4)];
            acc00 = fmaxf(acc00, xv0.x + wv0.x); acc00 = fmaxf(acc00, xv0.y + wv0.y);
            acc00 = fmaxf(acc00, xv0.z + wv0.z); acc00 = fmaxf(acc00, xv0.w + wv0.w);
            acc01 = fmaxf(acc01, xv0.x + wv1.x); acc01 = fmaxf(acc01, xv0.y + wv1.y);
            acc01 = fmaxf(acc01, xv0.z + wv1.z); acc01 = fmaxf(acc01, xv0.w + wv1.w);
            acc10 = fmaxf(acc10, xv1.x + wv0.x); acc10 = fmaxf(acc10, xv1.y + wv0.y);
            acc10 = fmaxf(acc10, xv1.z + wv0.z); acc10 = fmaxf(acc10, xv1.w + wv0.w);
            acc11 = fmaxf(acc11, xv1.x + wv1.x); acc11 = fmaxf(acc11, xv1.y + wv1.y);
            acc11 = fmaxf(acc11, xv1.z + wv1.z); acc11 = fmaxf(acc11, xv1.w + wv1.w);
        }
    }

    // ---- epilogue: add bias, store 4 outputs ----
    const int n0 = nBase + ty;
    const int n1 = n0 + 16;
    const int o0 = oBase + tx;
    const int o1 = o0 + 16;
    const float b0 = bias[o0];
    const float b1 = bias[o1];
    out[n0 * OUT_DIM + o0] = acc00 + b0;
    out[n0 * OUT_DIM + o1] = acc01 + b1;
    out[n1 * OUT_DIM + o0] = acc10 + b0;
    out[n1 * OUT_DIM + o1] = acc11 + b1;
}

extern "C" void kernel_launch(void* const* d_in, const int* in_sizes, int n_in,
                              void* d_out, int out_size)
{
    const float* x    = (const float*)d_in[0];   // [128, 1024]
    const float* w    = (const float*)d_in[1];   // [1024, 1024]
    const float* bias = (const float*)d_in[2];   // [1024]
    float* out = (float*)d_out;                  // [128, 1024]

    dim3 grid(OUT_DIM / BO, N_DIM / BM);         // 32 x 4 = 128 blocks
    tropical_kernel<<<grid, 256>>>(x, w, bias, out);
}